// round 15
// baseline (speedup 1.0000x reference)
#include <cuda_runtime.h>
#include <cuda.h>
#include <cuda_fp16.h>
#include <cstdint>
#include <math.h>

#define HIDDEN 2048
#define NHEADS 32
#define NKV    8
#define HD     64
#define INTER  8192
#define BATCH  2
#define QLEN   2048
#define KLEN   2048
#define MTOT   (BATCH*QLEN)

#if defined(__CUDA_ARCH_FEAT_SM103_ALL) || defined(__CUDA_ARCH_FEAT_SM100_ALL)
#define HAS_TCGEN05 1
#else
#define HAS_TCGEN05 0
#endif

// ---------------- scratch ----------------
__device__ __half g_wqh[(size_t)HIDDEN*HIDDEN];
__device__ __half g_woh[(size_t)HIDDEN*HIDDEN];
__device__ __half g_wgh[(size_t)INTER*HIDDEN];
__device__ __half g_wuh[(size_t)INTER*HIDDEN];
__device__ __half g_wdh[(size_t)HIDDEN*INTER];
__device__ __half g_kh [(size_t)BATCH*NKV*KLEN*HD];
__device__ __half g_vh [(size_t)BATCH*NKV*KLEN*HD];
__device__ __half g_n1h[(size_t)MTOT*HIDDEN];
__device__ __half g_qh [(size_t)MTOT*HIDDEN];
__device__ __half g_ath[(size_t)MTOT*HIDDEN];
__device__ __half g_n2h[(size_t)MTOT*HIDDEN];
__device__ __half g_gth[(size_t)MTOT*INTER];
__device__ __half g_ach[(size_t)MTOT*INTER];
__device__ float  g_hid[(size_t)MTOT*HIDDEN];

// ---------------- asm helpers ----------------
#define CPA(dst, src) asm volatile("cp.async.cg.shared.global [%0], [%1], 16;\n" :: "r"(dst), "l"(src))
#define CPC() asm volatile("cp.async.commit_group;\n")
#define CPW(N) asm volatile("cp.async.wait_group %0;\n" :: "n"(N))
#define LDSM4(r0,r1,r2,r3,addr) asm volatile("ldmatrix.sync.aligned.m8n8.x4.shared.b16 {%0,%1,%2,%3}, [%4];\n" \
    : "=r"(r0),"=r"(r1),"=r"(r2),"=r"(r3) : "r"(addr))
#define LDSM4T(r0,r1,r2,r3,addr) asm volatile("ldmatrix.sync.aligned.m8n8.x4.trans.shared.b16 {%0,%1,%2,%3}, [%4];\n" \
    : "=r"(r0),"=r"(r1),"=r"(r2),"=r"(r3) : "r"(addr))

__device__ __forceinline__ uint32_t swz128(uint32_t x){ return x ^ ((x>>3)&0x70); }

__device__ __forceinline__ uint32_t packh2(float a, float b){
    __half2 h = __floats2half2_rn(a, b);
    return *reinterpret_cast<uint32_t*>(&h);
}
__device__ __forceinline__ void mma16816(float* c, const uint32_t* a, uint32_t b0, uint32_t b1){
    asm volatile("mma.sync.aligned.m16n8k16.row.col.f32.f16.f16.f32 "
        "{%0,%1,%2,%3}, {%4,%5,%6,%7}, {%8,%9}, {%0,%1,%2,%3};"
        : "+f"(c[0]), "+f"(c[1]), "+f"(c[2]), "+f"(c[3])
        : "r"(a[0]), "r"(a[1]), "r"(a[2]), "r"(a[3]), "r"(b0), "r"(b1));
}
__device__ __forceinline__ float blockSum(float v){
    __shared__ float sh[8];
    __shared__ float res;
    int lane = threadIdx.x & 31, w = threadIdx.x >> 5;
    #pragma unroll
    for (int o=16;o;o>>=1) v += __shfl_xor_sync(0xffffffffu, v, o);
    if (lane==0) sh[w] = v;
    __syncthreads();
    if (w==0){
        float x = (lane < 8) ? sh[lane] : 0.f;
        #pragma unroll
        for (int o=4;o;o>>=1) x += __shfl_xor_sync(0xffffffffu, x, o);
        if (lane==0) res = x;
    }
    __syncthreads();
    return res;
}

// ---------------- converts ----------------
__global__ void f2h4(const float* __restrict__ s, __half* __restrict__ d, int n){
    int i = (blockIdx.x*256 + threadIdx.x)*4;
    if (i < n){
        float4 v = *(const float4*)(s+i);
        *(__half2*)(d+i)   = __floats2half2_rn(v.x, v.y);
        *(__half2*)(d+i+2) = __floats2half2_rn(v.z, v.w);
    }
}
__global__ void convkv(const float* __restrict__ k, const float* __restrict__ v,
                       __half* __restrict__ kd, __half* __restrict__ vd){
    int idx = blockIdx.x*256 + threadIdx.x;
    if (idx >= BATCH*KLEN*NKV*(HD/2)) return;
    int d2  = idx & 31;
    int kvh = (idx>>5) & 7;
    int kk  = (idx>>8) & 2047;
    int bb  = idx>>19;
    size_t src = (((size_t)(bb*KLEN+kk)*NKV + kvh)*HD) + d2*2;
    size_t dst = (((size_t)(bb*NKV+kvh)*KLEN + kk)*HD) + d2*2;
    float2 kf = *(const float2*)(k+src);
    float2 vf = *(const float2*)(v+src);
    *(__half2*)(kd+dst) = __floats2half2_rn(kf.x, kf.y);
    *(__half2*)(vd+dst) = __floats2half2_rn(vf.x, vf.y);
}

// ---------------- RMSNorm ----------------
__global__ void rmsnorm_h(const float* __restrict__ x, const float* __restrict__ w,
                          __half* __restrict__ o)
{
    size_t row = blockIdx.x;
    const float* xr = x + row*HIDDEN;
    __half* orow = o + row*HIDDEN;
    float s = 0.f;
    for (int i=threadIdx.x; i<HIDDEN; i+=256){ float v = xr[i]; s += v*v; }
    s = blockSum(s);
    float rs = rsqrtf(s*(1.f/HIDDEN) + 1e-5f);
    for (int i=threadIdx.x; i<HIDDEN; i+=256) orow[i] = __float2half(xr[i]*rs*w[i]);
}

// ==================== tcgen05 GEMM, warp-specialized TMA (R9 config) ====================
#define TCSTAGE 65536
#define TC_SMEM (3*TCSTAGE + 2048)

#if HAS_TCGEN05
__device__ __forceinline__ uint32_t elect_one_pred(){
    uint32_t pred;
    asm volatile("{\n\t.reg .pred p;\n\telect.sync _|p, 0xFFFFFFFF;\n\tselp.b32 %0, 1, 0, p;\n\t}" : "=r"(pred));
    return pred;
}
#define MBARRIER_INIT(addr, cnt) \
    asm volatile("mbarrier.init.shared.b64 [%0], %1;" :: "r"((uint32_t)(addr)), "r"((uint32_t)(cnt)) : "memory")
#define MBARRIER_EXPECT_TX(addr, bytes) \
    asm volatile("mbarrier.arrive.expect_tx.shared.b64 _, [%0], %1;" :: "r"((uint32_t)(addr)), "r"((uint32_t)(bytes)) : "memory")
#define TMA_2D(smem_addr, map_ptr, cx, cy, mbar) \
    asm volatile("cp.async.bulk.tensor.2d.shared::cta.global.tile.mbarrier::complete_tx::bytes " \
        "[%0], [%1, {%2, %3}], [%4];" \
        :: "r"((uint32_t)(smem_addr)), "l"(map_ptr), "r"((int)(cx)), "r"((int)(cy)), \
           "r"((uint32_t)(mbar)) : "memory")
__device__ __forceinline__ void mbar_wait(uint32_t mbar, uint32_t phase){
    asm volatile(
        "{\n\t.reg .pred P1;\n\t"
        "WAIT_%=:\n\t"
        "mbarrier.try_wait.parity.acquire.cta.shared::cta.b64 P1, [%0], %1, 0x989680;\n\t"
        "@P1 bra.uni DONE_%=;\n\t"
        "bra.uni WAIT_%=;\n\t"
        "DONE_%=:\n\t}"
        :: "r"(mbar), "r"(phase) : "memory");
}
static __device__ __forceinline__ uint64_t make_desc_sw128(uint32_t addr){
    const uint64_t base =
        (uint64_t(2)  << 61) | (uint64_t(1) << 46) | (uint64_t(64) << 32) | (uint64_t(1) << 16);
    return base | ((uint64_t)(addr >> 4) & 0x3FFF);
}
#define IDESC_N256 ((1u<<4) | (32u<<17) | (8u<<24))
#define IDESC_N128 ((1u<<4) | (16u<<17) | (8u<<24))
__device__ __forceinline__ void mma_f16_ss(uint32_t d, uint64_t ad, uint64_t bd, uint32_t idesc, uint32_t en){
    asm volatile(
        "{\n\t.reg .pred p;\n\tsetp.ne.u32 p, %5, 0;\n\t"
        "tcgen05.mma.cta_group::1.kind::f16 [%0], %1, %2, %3, {%4,%4,%4,%4}, p;\n\t}"
        :: "r"(d), "l"(ad), "l"(bd), "r"(idesc), "r"(0u), "r"(en) : "memory");
}
#define LDTM32(r, tmem_addr) \
    asm volatile( \
        "tcgen05.ld.sync.aligned.32x32b.x32.b32 " \
        "{%0, %1, %2, %3, %4, %5, %6, %7, " \
        " %8, %9, %10, %11, %12, %13, %14, %15, " \
        " %16, %17, %18, %19, %20, %21, %22, %23, " \
        " %24, %25, %26, %27, %28, %29, %30, %31}, [%32];" \
        : "=r"((r)[0]),  "=r"((r)[1]),  "=r"((r)[2]),  "=r"((r)[3]), \
          "=r"((r)[4]),  "=r"((r)[5]),  "=r"((r)[6]),  "=r"((r)[7]), \
          "=r"((r)[8]),  "=r"((r)[9]),  "=r"((r)[10]), "=r"((r)[11]), \
          "=r"((r)[12]), "=r"((r)[13]), "=r"((r)[14]), "=r"((r)[15]), \
          "=r"((r)[16]), "=r"((r)[17]), "=r"((r)[18]), "=r"((r)[19]), \
          "=r"((r)[20]), "=r"((r)[21]), "=r"((r)[22]), "=r"((r)[23]), \
          "=r"((r)[24]), "=r"((r)[25]), "=r"((r)[26]), "=r"((r)[27]), \
          "=r"((r)[28]), "=r"((r)[29]), "=r"((r)[30]), "=r"((r)[31]) \
        : "r"(tmem_addr))
#endif

// mode 0: Ch=acc; 1: Cf=acc+Resf; 3: Ch=acc*0.125
__global__ __launch_bounds__(256,1)
void gemm_tc(float* __restrict__ Cf, __half* __restrict__ Ch,
             const float* __restrict__ Resf,
             int M, int N, int K, int mode,
             const __grid_constant__ CUtensorMap amap,
             const __grid_constant__ CUtensorMap bmap)
{
#if HAS_TCGEN05
    extern __shared__ char smraw[];
    uint32_t smem0 = (uint32_t)__cvta_generic_to_shared(smraw);
    uint32_t base  = (smem0 + 1023u) & ~1023u;
    const uint32_t ctrl = base + 3*TCSTAGE;
    const uint32_t mbM = ctrl + 16;    // 3 mma-done barriers
    const uint32_t mbF = ctrl + 48;    // 3 full barriers
    const uint32_t mbX = ctrl + 80;    // final

    const int tid = threadIdx.x, lane = tid&31, warp = tid>>5;
    const int m0 = blockIdx.y*256, n0 = blockIdx.x*256;
    const int nkb = K >> 6;

    if (warp==0)
        asm volatile("tcgen05.alloc.cta_group::1.sync.aligned.shared::cta.b32 [%0], %1;"
            :: "r"(ctrl), "r"(512u) : "memory");
    if (tid==0){
        #pragma unroll
        for (int i=0;i<3;i++){ MBARRIER_INIT(mbM + i*8, 1); MBARRIER_INIT(mbF + i*8, 1); }
        MBARRIER_INIT(mbX, 1);
    }
    __syncthreads();
    uint32_t tmem; asm volatile("ld.shared.b32 %0, [%1];" : "=r"(tmem) : "r"(ctrl));

    uint32_t aAddr[3], bAddr[3];
    uint64_t aDesc[3], bDesc[3];
    #pragma unroll
    for (int s=0;s<3;s++){
        aAddr[s] = base + s*TCSTAGE;
        bAddr[s] = base + s*TCSTAGE + 32768;
        aDesc[s] = make_desc_sw128(aAddr[s]);
        bDesc[s] = make_desc_sw128(bAddr[s]);
    }

    if (warp==1){
        if (elect_one_pred()){
            #pragma unroll
            for (int c=0;c<3;c++){
                if (c < nkb){
                    MBARRIER_EXPECT_TX(mbF + c*8, 65536);
                    TMA_2D(aAddr[c], &amap, c*64, m0, mbF + c*8);
                    TMA_2D(bAddr[c], &bmap, c*64, n0, mbF + c*8);
                }
            }
            for (int t=3; t<nkb; t++){
                const int st = t%3;
                mbar_wait(mbM + st*8, (uint32_t)(((t-3)/3)&1));
                MBARRIER_EXPECT_TX(mbF + st*8, 65536);
                TMA_2D(aAddr[st], &amap, t*64, m0, mbF + st*8);
                TMA_2D(bAddr[st], &bmap, t*64, n0, mbF + st*8);
            }
        }
    } else if (warp==0){
        asm volatile("tcgen05.fence::after_thread_sync;" ::: "memory");
        if (elect_one_pred()){
            for (int t=0; t<nkb; t++){
                const int st = t%3;
                mbar_wait(mbF + st*8, (uint32_t)((t/3)&1));
                #pragma unroll
                for (int hf=0; hf<2; hf++){
                    #pragma unroll
                    for (int kc=0;kc<4;kc++){
                        mma_f16_ss(tmem + hf*256,
                                   aDesc[st] + hf*1024 + kc*2,
                                   bDesc[st] + kc*2, IDESC_N256,
                                   (t>0 || kc>0) ? 1u : 0u);
                    }
                }
                asm volatile("tcgen05.commit.cta_group::1.mbarrier::arrive::one.shared::cluster.b64 [%0];"
                    :: "r"(mbM + (uint32_t)st*8) : "memory");
            }
            asm volatile("tcgen05.commit.cta_group::1.mbarrier::arrive::one.shared::cluster.b64 [%0];"
                :: "r"(mbX) : "memory");
        }
    }

    mbar_wait(mbX, 0u);
    asm volatile("fence.proxy.async.shared::cta;" ::: "memory");
    asm volatile("tcgen05.fence::after_thread_sync;" ::: "memory");
    __syncthreads();

    // epilogue: LDTM -> direct coalesced gmem (lane owns a 32-col contiguous run)
    const int hf  = warp>>2;           // M half
    const int wsb = warp&3;            // subpartition
    const int row = m0 + hf*128 + wsb*32 + lane;

    #pragma unroll
    for (int cc=0; cc<8; cc++){
        uint32_t r[32];
        LDTM32(r, tmem + hf*256 + cc*32);
        asm volatile("tcgen05.wait::ld.sync.aligned;" ::: "memory");
        const int col = n0 + cc*32;
        if (mode==1){
            float* dst = Cf + (size_t)row*N + col;
            const float* rsp = Resf + (size_t)row*N + col;
            #pragma unroll
            for (int j=0;j<32;j+=4){
                float4 rf = *(const float4*)(rsp + j);
                *(float4*)(dst + j) = make_float4(
                    __uint_as_float(r[j])   + rf.x, __uint_as_float(r[j+1]) + rf.y,
                    __uint_as_float(r[j+2]) + rf.z, __uint_as_float(r[j+3]) + rf.w);
            }
        } else if (mode==3){
            __half* dst = Ch + (size_t)row*N + col;
            #pragma unroll
            for (int j=0;j<32;j+=2)
                *(__half2*)(dst + j) = __floats2half2_rn(__uint_as_float(r[j])*0.125f,
                                                         __uint_as_float(r[j+1])*0.125f);
        } else {
            __half* dst = Ch + (size_t)row*N + col;
            #pragma unroll
            for (int j=0;j<32;j+=2)
                *(__half2*)(dst + j) = __floats2half2_rn(__uint_as_float(r[j]),
                                                         __uint_as_float(r[j+1]));
        }
    }

    asm volatile("tcgen05.fence::before_thread_sync;" ::: "memory");
    __syncthreads();
    if (warp==0)
        asm volatile("tcgen05.dealloc.cta_group::1.sync.aligned.b32 %0, %1;" :: "r"(tmem), "r"(512u));
#endif
}

// ==================== fused gate+up+SiLU, warp-specialized TMA (R9 config) ====================
__global__ __launch_bounds__(256,1)
void gemm_tc_gu(__half* __restrict__ Ch, int M, int N, int K,
                const __grid_constant__ CUtensorMap amap,
                const __grid_constant__ CUtensorMap gmap,
                const __grid_constant__ CUtensorMap umap)
{
#if HAS_TCGEN05
    extern __shared__ char smraw[];
    uint32_t smem0 = (uint32_t)__cvta_generic_to_shared(smraw);
    uint32_t base  = (smem0 + 1023u) & ~1023u;
    const uint32_t ctrl = base + 3*TCSTAGE;
    const uint32_t mbM = ctrl + 16;
    const uint32_t mbF = ctrl + 48;
    const uint32_t mbX = ctrl + 80;

    const int tid = threadIdx.x, lane = tid&31, warp = tid>>5;
    const int m0 = blockIdx.y*256, n0 = blockIdx.x*128;
    const int nkb = K >> 6;

    if (warp==0)
        asm volatile("tcgen05.alloc.cta_group::1.sync.aligned.shared::cta.b32 [%0], %1;"
            :: "r"(ctrl), "r"(512u) : "memory");
    if (tid==0){
        #pragma unroll
        for (int i=0;i<3;i++){ MBARRIER_INIT(mbM + i*8, 1); MBARRIER_INIT(mbF + i*8, 1); }
        MBARRIER_INIT(mbX, 1);
    }
    __syncthreads();
    uint32_t tmem; asm volatile("ld.shared.b32 %0, [%1];" : "=r"(tmem) : "r"(ctrl));

    uint32_t aAddr[3], gAddr[3], uAddr[3];
    uint64_t aDesc[3], gDesc[3], uDesc[3];
    #pragma unroll
    for (int s=0;s<3;s++){
        aAddr[s] = base + s*TCSTAGE;
        gAddr[s] = base + s*TCSTAGE + 32768;
        uAddr[s] = base + s*TCSTAGE + 49152;
        aDesc[s] = make_desc_sw128(aAddr[s]);
        gDesc[s] = make_desc_sw128(gAddr[s]);
        uDesc[s] = make_desc_sw128(uAddr[s]);
    }

    if (warp==1){
        if (elect_one_pred()){
            #pragma unroll
            for (int c=0;c<3;c++){
                if (c < nkb){
                    MBARRIER_EXPECT_TX(mbF + c*8, 65536);
                    TMA_2D(aAddr[c], &amap, c*64, m0, mbF + c*8);
                    TMA_2D(gAddr[c], &gmap, c*64, n0, mbF + c*8);
                    TMA_2D(uAddr[c], &umap, c*64, n0, mbF + c*8);
                }
            }
            for (int t=3; t<nkb; t++){
                const int st = t%3;
                mbar_wait(mbM + st*8, (uint32_t)(((t-3)/3)&1));
                MBARRIER_EXPECT_TX(mbF + st*8, 65536);
                TMA_2D(aAddr[st], &amap, t*64, m0, mbF + st*8);
                TMA_2D(gAddr[st], &gmap, t*64, n0, mbF + st*8);
                TMA_2D(uAddr[st], &umap, t*64, n0, mbF + st*8);
            }
        }
    } else if (warp==0){
        asm volatile("tcgen05.fence::after_thread_sync;" ::: "memory");
        if (elect_one_pred()){
            for (int t=0; t<nkb; t++){
                const int st = t%3;
                mbar_wait(mbF + st*8, (uint32_t)((t/3)&1));
                #pragma unroll
                for (int hf=0; hf<2; hf++){
                    #pragma unroll
                    for (int kc=0;kc<4;kc++){
                        uint32_t e = (t>0 || kc>0) ? 1u : 0u;
                        mma_f16_ss(tmem + hf*128,
                                   aDesc[st] + hf*1024 + kc*2,
                                   gDesc[st] + kc*2, IDESC_N128, e);
                        mma_f16_ss(tmem + 256 + hf*128,
                                   aDesc[st] + hf*1024 + kc*2,
                                   uDesc[st] + kc*2, IDESC_N128, e);
                    }
                }
                asm volatile("tcgen05.commit.cta_group::1.mbarrier::arrive::one.shared::cluster.b64 [%0];"
                    :: "r"(mbM + (uint32_t)st*8) : "memory");
            }
            asm volatile("tcgen05.commit.cta_group::1.mbarrier::arrive::one.shared::cluster.b64 [%0];"
                :: "r"(mbX) : "memory");
        }
    }

    mbar_wait(mbX, 0u);
    asm volatile("tcgen05.fence::after_thread_sync;" ::: "memory");
    __syncthreads();

    // epilogue: silu(gate)*up straight from TMEM, direct stores
    const int hf  = warp>>2;
    const int wsb = warp&3;
    const int row = hf*128 + wsb*32 + lane;

    #pragma unroll
    for (int cc=0; cc<4; cc++){
        uint32_t rg[32], ru[32];
        LDTM32(rg, tmem + hf*128 + cc*32);
        LDTM32(ru, tmem + 256 + hf*128 + cc*32);
        asm volatile("tcgen05.wait::ld.sync.aligned;" ::: "memory");
        __half* dst = Ch + (size_t)(m0 + row)*N + (n0 + cc*32);
        #pragma unroll
        for (int j=0;j<32;j+=2){
            float g0 = __uint_as_float(rg[j]),   g1 = __uint_as_float(rg[j+1]);
            float u0 = __uint_as_float(ru[j]),   u1 = __uint_as_float(ru[j+1]);
            float v0 = (g0/(1.f+__expf(-g0)))*u0;
            float v1 = (g1/(1.f+__expf(-g1)))*u1;
            *(__half2*)(dst + j) = __floats2half2_rn(v0, v1);
        }
    }

    asm volatile("tcgen05.fence::before_thread_sync;" ::: "memory");
    __syncthreads();
    if (warp==0)
        asm volatile("tcgen05.dealloc.cta_group::1.sync.aligned.b32 %0, %1;" :: "r"(tmem), "r"(512u));
#endif
}

// ---------------- fallback fp16 mma.sync GEMM ----------------
#define SPITCH 72
#define STAGEB (128*SPITCH*2)

__global__ __launch_bounds__(256,2)
void gemm16(const __half* __restrict__ A, const __half* __restrict__ B,
            float* __restrict__ Cf, __half* __restrict__ Ch,
            const __half* __restrict__ Resh, const float* __restrict__ Resf,
            int M, int N, int K, int mode)
{
    extern __shared__ __half smf[];
    uint32_t asBase = (uint32_t)__cvta_generic_to_shared(smf);
    uint32_t bsBase = asBase + 2*STAGEB;

    const int tid = threadIdx.x, lane = tid&31, warp = tid>>5;
    const int g = lane>>2, tg = lane&3;
    const int wm = (warp&1)*64, wn = (warp>>1)*32;
    const int m0 = blockIdx.y*128, n0 = blockIdx.x*128;

    const int crow = tid>>3;
    const int cchk = tid&7;
    const uint32_t sOff = (uint32_t)(crow*SPITCH*2 + cchk*16);
    const __half* aSrc = A + (size_t)(m0+crow)*K + cchk*8;
    const __half* bSrc = B + (size_t)(n0+crow)*K + cchk*8;

    float acc[4][4][4];
    #pragma unroll
    for (int i=0;i<4;i++)
        #pragma unroll
        for (int j=0;j<4;j++){ acc[i][j][0]=0.f; acc[i][j][1]=0.f; acc[i][j][2]=0.f; acc[i][j][3]=0.f; }

    const int nkb = K >> 6;
    {
        uint32_t ao = asBase + sOff, bo = bsBase + sOff;
        #pragma unroll
        for (int i=0;i<4;i++){
            CPA(ao + i*32*SPITCH*2, aSrc + (size_t)i*32*K);
            CPA(bo + i*32*SPITCH*2, bSrc + (size_t)i*32*K);
        }
        CPC();
    }

    for (int kb=0; kb<nkb; kb++){
        const int st = kb & 1;
        if (kb+1 < nkb){
            uint32_t ao = asBase + (st^1)*STAGEB + sOff;
            uint32_t bo = bsBase + (st^1)*STAGEB + sOff;
            const __half* ap = aSrc + (size_t)(kb+1)*64;
            const __half* bp = bSrc + (size_t)(kb+1)*64;
            #pragma unroll
            for (int i=0;i<4;i++){
                CPA(ao + i*32*SPITCH*2, ap + (size_t)i*32*K);
                CPA(bo + i*32*SPITCH*2, bp + (size_t)i*32*K);
            }
            CPC();
            CPW(1);
        } else {
            CPW(0);
        }
        __syncthreads();

        const uint32_t aW = asBase + st*STAGEB;
        const uint32_t bW = bsBase + st*STAGEB;
        #pragma unroll
        for (int kc=0;kc<4;kc++){
            uint32_t af[4][4], bf[2][4];
            #pragma unroll
            for (int mi=0;mi<4;mi++){
                int r = wm + mi*16 + (lane&15);
                int c = kc*16 + (lane>>4)*8;
                LDSM4(af[mi][0],af[mi][1],af[mi][2],af[mi][3], aW + (uint32_t)(r*SPITCH + c)*2);
            }
            #pragma unroll
            for (int nj=0;nj<2;nj++){
                int r = wn + nj*16 + (lane>>4)*8 + (lane&7);
                int c = kc*16 + ((lane>>3)&1)*8;
                LDSM4(bf[nj][0],bf[nj][1],bf[nj][2],bf[nj][3], bW + (uint32_t)(r*SPITCH + c)*2);
            }
            #pragma unroll
            for (int mi=0;mi<4;mi++){
                #pragma unroll
                for (int nj=0;nj<2;nj++){
                    mma16816(acc[mi][2*nj  ], af[mi], bf[nj][0], bf[nj][1]);
                    mma16816(acc[mi][2*nj+1], af[mi], bf[nj][2], bf[nj][3]);
                }
            }
        }
        __syncthreads();
    }

    #pragma unroll
    for (int mi=0;mi<4;mi++){
        #pragma unroll
        for (int ni=0;ni<4;ni++){
            int r0 = m0 + wm + mi*16 + g;
            int r1 = r0 + 8;
            int c  = n0 + wn + ni*8 + 2*tg;
            size_t o0 = (size_t)r0*N + c;
            size_t o1 = (size_t)r1*N + c;
            float v0=acc[mi][ni][0], v1=acc[mi][ni][1], v2=acc[mi][ni][2], v3=acc[mi][ni][3];
            if (mode == 1){
                v0 += Resf[o0]; v1 += Resf[o0+1]; v2 += Resf[o1]; v3 += Resf[o1+1];
                *(float2*)&Cf[o0] = make_float2(v0,v1);
                *(float2*)&Cf[o1] = make_float2(v2,v3);
            } else if (mode == 2){
                float g0 = __half2float(Resh[o0]), g1 = __half2float(Resh[o0+1]);
                float g2 = __half2float(Resh[o1]), g3 = __half2float(Resh[o1+1]);
                v0 *= g0/(1.f+__expf(-g0)); v1 *= g1/(1.f+__expf(-g1));
                v2 *= g2/(1.f+__expf(-g2)); v3 *= g3/(1.f+__expf(-g3));
                *(__half2*)&Ch[o0] = __floats2half2_rn(v0,v1);
                *(__half2*)&Ch[o1] = __floats2half2_rn(v2,v3);
            } else if (mode == 3){
                *(__half2*)&Ch[o0] = __floats2half2_rn(v0*0.125f, v1*0.125f);
                *(__half2*)&Ch[o1] = __floats2half2_rn(v2*0.125f, v3*0.125f);
            } else {
                *(__half2*)&Ch[o0] = __floats2half2_rn(v0,v1);
                *(__half2*)&Ch[o1] = __floats2half2_rn(v2,v3);
            }
        }
    }
}

// ---------------- flash attention (swizzled stages, occ 2) ----------------
#define FSTG 16384
#define FSMEM (4*FSTG)

__global__ __launch_bounds__(256,2)
void flash4(const __half* __restrict__ qh, const __half* __restrict__ kh,
            const __half* __restrict__ vh, __half* __restrict__ oh,
            const int* __restrict__ cuq, const int* __restrict__ cuk)
{
    extern __shared__ __half sm[];
    uint32_t ksBase = (uint32_t)__cvta_generic_to_shared(sm);
    uint32_t vsBase = ksBase + 2*FSTG;

    const int tid  = threadIdx.x;
    const int lane = tid & 31, warp = tid >> 5;
    const int g = lane >> 2, tg = lane & 3;
    const int bh = blockIdx.y;
    const int b = bh >> 5, h = bh & 31, kv = h >> 2;
    const int q0 = blockIdx.x * 128;
    const int wq = warp * 16;

    const int cq1 = cuq[1], cq2 = cuq[2];
    const int ck1 = cuk[1], ck2 = cuk[2];

    const int qg0 = q0 + wq + g, qg1 = qg0 + 8;
    const __half* qr0 = qh + ((size_t)(b*QLEN + qg0))*HIDDEN + h*HD;
    const __half* qr1 = qh + ((size_t)(b*QLEN + qg1))*HIDDEN + h*HD;
    uint32_t qf[4][4];
    #pragma unroll
    for (int kc=0;kc<4;kc++){
        qf[kc][0] = *(const uint32_t*)(qr0 + kc*16 + 2*tg);
        qf[kc][1] = *(const uint32_t*)(qr1 + kc*16 + 2*tg);
        qf[kc][2] = *(const uint32_t*)(qr0 + kc*16 + 2*tg + 8);
        qf[kc][3] = *(const uint32_t*)(qr1 + kc*16 + 2*tg + 8);
    }

    const int sq0 = (qg0>=cq1)+(qg0>=cq2);
    const int sq1 = (qg1>=cq1)+(qg1>=cq2);
    const int wlo = q0 + wq, whi = wlo + 15;
    const int sqa = (wlo>=cq1)+(wlo>=cq2);
    const int sqb = (whi>=cq1)+(whi>=cq2);

    float oacc[8][4];
    #pragma unroll
    for (int i=0;i<8;i++){ oacc[i][0]=0.f; oacc[i][1]=0.f; oacc[i][2]=0.f; oacc[i][3]=0.f; }
    float mr0 = -1e20f, mr1 = -1e20f, l0 = 0.f, l1 = 0.f;

    int segA = (q0>=cq1)+(q0>=cq2);
    int segB = (q0+127>=cq1)+(q0+127>=cq2);
    int klo, khi;
    if (segA == segB){
        int klos = (segA==0) ? 0 : ((segA==1) ? ck1 : ck2);
        int khis = (segA==0) ? ck1 : ((segA==1) ? ck2 : KLEN);
        klo = klos;
        khi = min(khis, q0+128);
    } else { klo = 0; khi = q0+128; }
    const int t0 = klo >> 7, t1 = (khi + 127) >> 7;

    const __half* kBase = kh + (size_t)(b*NKV+kv)*KLEN*HD;
    const __half* vBase = vh + (size_t)(b*NKV+kv)*KLEN*HD;
    const int crow = tid>>3, cchk = tid&7;
    uint32_t stOff[4];
    #pragma unroll
    for (int i=0;i<4;i++) stOff[i] = swz128((uint32_t)((crow + i*32)*128 + cchk*16));

    {
        const __half* kp = kBase + (size_t)(t0*128 + crow)*HD + cchk*8;
        const __half* vp = vBase + (size_t)(t0*128 + crow)*HD + cchk*8;
        #pragma unroll
        for (int i=0;i<4;i++){
            CPA(ksBase + stOff[i], kp + (size_t)i*32*HD);
            CPA(vsBase + stOff[i], vp + (size_t)i*32*HD);
        }
        CPC();
    }

    for (int t=t0; t<t1; t++){
        const int st = (t - t0) & 1;
        const int k0 = t << 7;
        if (t+1 < t1){
            uint32_t ko = ksBase + (st^1)*FSTG;
            uint32_t vo = vsBase + (st^1)*FSTG;
            const __half* kp = kBase + (size_t)((t+1)*128 + crow)*HD + cchk*8;
            const __half* vp = vBase + (size_t)((t+1)*128 + crow)*HD + cchk*8;
            #pragma unroll
            for (int i=0;i<4;i++){
                CPA(ko + stOff[i], kp + (size_t)i*32*HD);
                CPA(vo + stOff[i], vp + (size_t)i*32*HD);
            }
            CPC();
            CPW(1);
        } else {
            CPW(0);
        }
        __syncthreads();

        const uint32_t kW = ksBase + st*FSTG;
        const uint32_t vW = vsBase + st*FSTG;

        float sacc[16][4];
        #pragma unroll
        for (int ni=0;ni<16;ni++){ sacc[ni][0]=0.f; sacc[ni][1]=0.f; sacc[ni][2]=0.f; sacc[ni][3]=0.f; }
        #pragma unroll
        for (int kc=0;kc<4;kc++){
            #pragma unroll
            for (int nj=0;nj<8;nj++){
                uint32_t b0,b1,b2,b3;
                int r = nj*16 + (lane>>4)*8 + (lane&7);
                int cb = kc*32 + ((lane>>3)&1)*16;
                LDSM4(b0,b1,b2,b3, kW + swz128((uint32_t)(r*128 + cb)));
                mma16816(sacc[2*nj  ], qf[kc], b0, b1);
                mma16816(sacc[2*nj+1], qf[kc], b2, b3);
            }
        }

        int s_k0   = (k0>=ck1)+(k0>=ck2);
        int s_k127 = (k0+127>=ck1)+(k0+127>=ck2);
        bool fullok = (k0+127 <= wlo) && (s_k0==sqa) && (s_k127==sqa) && (sqa==sqb);
        if (!fullok){
            #pragma unroll
            for (int ni=0;ni<16;ni++){
                int kg = k0 + ni*8 + 2*tg;
                int sk0 = (kg>=ck1)+(kg>=ck2);
                int sk1 = (kg+1>=ck1)+(kg+1>=ck2);
                if (!((kg   <= qg0) && (sk0==sq0))) sacc[ni][0] = -1e30f;
                if (!((kg+1 <= qg0) && (sk1==sq0))) sacc[ni][1] = -1e30f;
                if (!((kg   <= qg1) && (sk0==sq1))) sacc[ni][2] = -1e30f;
                if (!((kg+1 <= qg1) && (sk1==sq1))) sacc[ni][3] = -1e30f;
            }
        }

        float tm0 = -1e20f, tm1 = -1e20f;
        #pragma unroll
        for (int ni=0;ni<16;ni++){
            tm0 = fmaxf(tm0, fmaxf(sacc[ni][0], sacc[ni][1]));
            tm1 = fmaxf(tm1, fmaxf(sacc[ni][2], sacc[ni][3]));
        }
        tm0 = fmaxf(tm0, __shfl_xor_sync(0xffffffffu, tm0, 1));
        tm0 = fmaxf(tm0, __shfl_xor_sync(0xffffffffu, tm0, 2));
        tm1 = fmaxf(tm1, __shfl_xor_sync(0xffffffffu, tm1, 1));
        tm1 = fmaxf(tm1, __shfl_xor_sync(0xffffffffu, tm1, 2));
        float mn0 = fmaxf(mr0, tm0), mn1 = fmaxf(mr1, tm1);
        float sc0 = __expf(mr0 - mn0), sc1 = __expf(mr1 - mn1);
        l0 *= sc0; l1 *= sc1;
        #pragma unroll
        for (int nd=0;nd<8;nd++){
            oacc[nd][0]*=sc0; oacc[nd][1]*=sc0; oacc[nd][2]*=sc1; oacc[nd][3]*=sc1;
        }
        uint32_t pf[8][4];
        float rs0 = 0.f, rs1 = 0.f;
        #pragma unroll
        for (int j=0;j<8;j++){
            float p00 = __expf(sacc[2*j][0]-mn0),   p01 = __expf(sacc[2*j][1]-mn0);
            float p10 = __expf(sacc[2*j][2]-mn1),   p11 = __expf(sacc[2*j][3]-mn1);
            float q00 = __expf(sacc[2*j+1][0]-mn0), q01 = __expf(sacc[2*j+1][1]-mn0);
            float q10 = __expf(sacc[2*j+1][2]-mn1), q11 = __expf(sacc[2*j+1][3]-mn1);
            rs0 += p00+p01+q00+q01;
            rs1 += p10+p11+q10+q11;
            pf[j][0] = packh2(p00,p01);
            pf[j][1] = packh2(p10,p11);
            pf[j][2] = packh2(q00,q01);
            pf[j][3] = packh2(q10,q11);
        }
        rs0 += __shfl_xor_sync(0xffffffffu, rs0, 1);
        rs0 += __shfl_xor_sync(0xffffffffu, rs0, 2);
        rs1 += __shfl_xor_sync(0xffffffffu, rs1, 1);
        rs1 += __shfl_xor_sync(0xffffffffu, rs1, 2);
        l0 += rs0; l1 += rs1;
        mr0 = mn0; mr1 = mn1;

        #pragma unroll
        for (int j=0;j<8;j++){
            #pragma unroll
            for (int dq=0;dq<4;dq++){
                uint32_t b0,b1,b2,b3;
                int r = j*16 + ((lane>>3)&1)*8 + (lane&7);
                int cb = dq*32 + (lane>>4)*16;
                LDSM4T(b0,b1,b2,b3, vW + swz128((uint32_t)(r*128 + cb)));
                mma16816(oacc[2*dq  ], pf[j], b0, b1);
                mma16816(oacc[2*dq+1], pf[j], b2, b3);
            }
        }
        __syncthreads();
    }

    float inv0 = (l0 > 0.f) ? 1.f/l0 : 0.f;
    float inv1 = (l1 > 0.f) ? 1.f/l1 : 0.f;
    __half* or0 = oh + ((size_t)(b*QLEN + qg0))*HIDDEN + h*HD;
    __half* or1 = oh + ((size_t)(b*QLEN + qg1))*HIDDEN + h*HD;
    #pragma unroll
    for (int nd=0;nd<8;nd++){
        int c = nd*8 + 2*tg;
        *(__half2*)&or0[c] = __floats2half2_rn(oacc[nd][0]*inv0, oacc[nd][1]*inv0);
        *(__half2*)&or1[c] = __floats2half2_rn(oacc[nd][2]*inv1, oacc[nd][3]*inv1);
    }
}

// ---------------- host tensormap helper ----------------
typedef CUresult (*EncTiledFn)(CUtensorMap*, CUtensorMapDataType, cuuint32_t, void*,
                               const cuuint64_t*, const cuuint64_t*, const cuuint32_t*, const cuuint32_t*,
                               CUtensorMapInterleave, CUtensorMapSwizzle,
                               CUtensorMapL2promotion, CUtensorMapFloatOOBfill);

static bool enc_map(EncTiledFn enc, CUtensorMap* m, void* ptr, uint64_t Kdim, uint64_t Ndim, uint32_t box1){
    cuuint64_t dims[2]    = {(cuuint64_t)Kdim, (cuuint64_t)Ndim};
    cuuint64_t strides[1] = {(cuuint64_t)(Kdim*2)};
    cuuint32_t box[2]     = {64u, box1};
    cuuint32_t es[2]      = {1u, 1u};
    return enc(m, CU_TENSOR_MAP_DATA_TYPE_UINT16, 2, ptr, dims, strides, box, es,
               CU_TENSOR_MAP_INTERLEAVE_NONE, CU_TENSOR_MAP_SWIZZLE_128B,
               CU_TENSOR_MAP_L2_PROMOTION_L2_128B, CU_TENSOR_MAP_FLOAT_OOB_FILL_NONE) == CUDA_SUCCESS;
}

// ---------------- launch ----------------
extern "C" void kernel_launch(void* const* d_in, const int* in_sizes, int n_in,
                              void* d_out, int out_size)
{
    const float* hs   = (const float*)d_in[0];
    const float* kst  = (const float*)d_in[1];
    const float* vst  = (const float*)d_in[2];
    const float* wln1 = (const float*)d_in[4];
    const float* wln2 = (const float*)d_in[5];
    const float* wq   = (const float*)d_in[6];
    const float* wo   = (const float*)d_in[7];
    const float* wg   = (const float*)d_in[8];
    const float* wu   = (const float*)d_in[9];
    const float* wd   = (const float*)d_in[10];
    const int*   cuq  = (const int*)d_in[11];
    const int*   cuk  = (const int*)d_in[12];
    float* out = (float*)d_out;

    __half *wqh,*woh,*wgh,*wuh,*wdh,*kh,*vh,*n1h,*qh,*ath,*n2h,*gth,*ach;
    float *hid;
    cudaGetSymbolAddress((void**)&wqh, g_wqh);
    cudaGetSymbolAddress((void**)&woh, g_woh);
    cudaGetSymbolAddress((void**)&wgh, g_wgh);
    cudaGetSymbolAddress((void**)&wuh, g_wuh);
    cudaGetSymbolAddress((void**)&wdh, g_wdh);
    cudaGetSymbolAddress((void**)&kh,  g_kh);
    cudaGetSymbolAddress((void**)&vh,  g_vh);
    cudaGetSymbolAddress((void**)&n1h, g_n1h);
    cudaGetSymbolAddress((void**)&qh,  g_qh);
    cudaGetSymbolAddress((void**)&ath, g_ath);
    cudaGetSymbolAddress((void**)&n2h, g_n2h);
    cudaGetSymbolAddress((void**)&gth, g_gth);
    cudaGetSymbolAddress((void**)&ach, g_ach);
    cudaGetSymbolAddress((void**)&hid, g_hid);

    cudaFuncAttributes fa; fa.numRegs = 0;
    cudaFuncGetAttributes(&fa, (const void*)gemm_tc);
    bool use_tc = (fa.numRegs > 32);

    CUtensorMap mAn1{}, mAat{}, mAn2{}, mAac{}, mWq{}, mWo{}, mWg{}, mWu{}, mWd{};
    if (use_tc){
        void* p = nullptr;
        cudaDriverEntryPointQueryResult st;
        if (cudaGetDriverEntryPoint("cuTensorMapEncodeTiled", &p, cudaEnableDefault, &st) == cudaSuccess
            && st == cudaDriverEntryPointSuccess && p){
            EncTiledFn enc = (EncTiledFn)p;
            bool ok = enc_map(enc, &mAn1, n1h, HIDDEN, MTOT, 256)
                   && enc_map(enc, &mAat, ath, HIDDEN, MTOT, 256)
                   && enc_map(enc, &mAn2, n2h, HIDDEN, MTOT, 256)
                   && enc_map(enc, &mAac, ach, INTER,  MTOT, 256)
                   && enc_map(enc, &mWq,  wqh, HIDDEN, HIDDEN, 256)
                   && enc_map(enc, &mWo,  woh, HIDDEN, HIDDEN, 256)
                   && enc_map(enc, &mWg,  wgh, HIDDEN, INTER, 128)
                   && enc_map(enc, &mWu,  wuh, HIDDEN, INTER, 128)
                   && enc_map(enc, &mWd,  wdh, INTER,  HIDDEN, 256);
            if (!ok) use_tc = false;
        } else {
            use_tc = false;
        }
    }

    cudaFuncSetAttribute(flash4, cudaFuncAttributeMaxDynamicSharedMemorySize, FSMEM);
    if (use_tc){
        cudaFuncSetAttribute(gemm_tc,    cudaFuncAttributeMaxDynamicSharedMemorySize, TC_SMEM);
        cudaFuncSetAttribute(gemm_tc_gu, cudaFuncAttributeMaxDynamicSharedMemorySize, TC_SMEM);
    } else {
        cudaFuncSetAttribute(gemm16, cudaFuncAttributeMaxDynamicSharedMemorySize, 4*STAGEB);
    }

    const int HH = HIDDEN*HIDDEN, IH = INTER*HIDDEN;

    cudaStream_t sB;
    cudaStreamCreateWithFlags(&sB, cudaStreamNonBlocking);
    cudaEvent_t eF, eQ, eK, eJ;
    cudaEventCreateWithFlags(&eF, cudaEventDisableTiming);
    cudaEventCreateWithFlags(&eQ, cudaEventDisableTiming);
    cudaEventCreateWithFlags(&eK, cudaEventDisableTiming);
    cudaEventCreateWithFlags(&eJ, cudaEventDisableTiming);
    cudaEventRecord(eF, 0);
    cudaStreamWaitEvent(sB, eF, 0);

    f2h4<<<(HH/4+255)/256, 256, 0, sB>>>(wq, wqh, HH);
    cudaEventRecord(eQ, sB);
    rmsnorm_h<<<MTOT, 256>>>(hs, wln1, n1h);
    convkv<<<(BATCH*KLEN*NKV*(HD/2)+255)/256, 256, 0, sB>>>(kst, vst, kh, vh);
    cudaEventRecord(eK, sB);

    cudaStreamWaitEvent(0, eQ, 0);
    if (use_tc)
        gemm_tc<<<dim3(HIDDEN/256, MTOT/256), 256, TC_SMEM>>>(nullptr, qh, nullptr, MTOT, HIDDEN, HIDDEN, 3, mAn1, mWq);
    else
        gemm16<<<dim3(HIDDEN/128, MTOT/128), 256, 4*STAGEB>>>(n1h, wqh, nullptr, qh, nullptr, nullptr, MTOT, HIDDEN, HIDDEN, 3);

    cudaStreamWaitEvent(0, eK, 0);
    flash4<<<dim3(QLEN/128, BATCH*NHEADS), 256, FSMEM>>>(qh, kh, vh, ath, cuq, cuk);

    f2h4<<<(HH/4+255)/256, 256, 0, sB>>>(wo, woh, HH);
    f2h4<<<(IH/4+255)/256, 256, 0, sB>>>(wg, wgh, IH);
    f2h4<<<(IH/4+255)/256, 256, 0, sB>>>(wu, wuh, IH);
    f2h4<<<(IH/4+255)/256, 256, 0, sB>>>(wd, wdh, IH);
    cudaEventRecord(eJ, sB);
    cudaStreamWaitEvent(0, eJ, 0);

    if (use_tc){
        gemm_tc<<<dim3(HIDDEN/256, MTOT/256), 256, TC_SMEM>>>(hid, nullptr, hs, MTOT, HIDDEN, HIDDEN, 1, mAat, mWo);
        rmsnorm_h<<<MTOT, 256>>>(hid, wln2, n2h);
        gemm_tc_gu<<<dim3(INTER/128, MTOT/256), 256, TC_SMEM>>>(ach, MTOT, INTER, HIDDEN, mAn2, mWg, mWu);
        gemm_tc<<<dim3(HIDDEN/256, MTOT/256), 256, TC_SMEM>>>(out, nullptr, hid, MTOT, HIDDEN, INTER, 1, mAac, mWd);
    } else {
        gemm16<<<dim3(HIDDEN/128, MTOT/128), 256, 4*STAGEB>>>(ath, woh, hid, nullptr, nullptr, hs, MTOT, HIDDEN, HIDDEN, 1);
        rmsnorm_h<<<MTOT, 256>>>(hid, wln2, n2h);
        gemm16<<<dim3(INTER/128, MTOT/128), 256, 4*STAGEB>>>(n2h, wgh, nullptr, gth, nullptr, nullptr, MTOT, INTER, HIDDEN, 0);
        gemm16<<<dim3(INTER/128, MTOT/128), 256, 4*STAGEB>>>(n2h, wuh, nullptr, ach, gth, nullptr, MTOT, INTER, HIDDEN, 2);
        gemm16<<<dim3(HIDDEN/128, MTOT/128), 256, 4*STAGEB>>>(ach, wdh, out, nullptr, nullptr, hid, MTOT, HIDDEN, INTER, 1);
    }

    cudaEventDestroy(eF);
    cudaEventDestroy(eQ);
    cudaEventDestroy(eK);
    cudaEventDestroy(eJ);
    cudaStreamDestroy(sB);
}

// round 17
// speedup vs baseline: 1.0840x; 1.0840x over previous
#include <cuda_runtime.h>
#include <cuda.h>
#include <cuda_fp16.h>
#include <cstdint>
#include <math.h>

#define HIDDEN 2048
#define NHEADS 32
#define NKV    8
#define HD     64
#define INTER  8192
#define BATCH  2
#define QLEN   2048
#define KLEN   2048
#define MTOT   (BATCH*QLEN)

#if defined(__CUDA_ARCH_FEAT_SM103_ALL) || defined(__CUDA_ARCH_FEAT_SM100_ALL)
#define HAS_TCGEN05 1
#else
#define HAS_TCGEN05 0
#endif

// ---------------- scratch ----------------
__device__ __half g_wqh[(size_t)HIDDEN*HIDDEN];
__device__ __half g_woh[(size_t)HIDDEN*HIDDEN];
__device__ __half g_wgh[(size_t)INTER*HIDDEN];
__device__ __half g_wuh[(size_t)INTER*HIDDEN];
__device__ __half g_wdh[(size_t)HIDDEN*INTER];
__device__ __half g_kh [(size_t)BATCH*NKV*KLEN*HD];
__device__ __half g_vh [(size_t)BATCH*NKV*KLEN*HD];
__device__ __half g_n1h[(size_t)MTOT*HIDDEN];
__device__ __half g_qh [(size_t)MTOT*HIDDEN];
__device__ __half g_ath[(size_t)MTOT*HIDDEN];
__device__ __half g_n2h[(size_t)MTOT*HIDDEN];
__device__ __half g_gth[(size_t)MTOT*INTER];
__device__ __half g_ach[(size_t)MTOT*INTER];
__device__ float  g_hid[(size_t)MTOT*HIDDEN];

// ---------------- asm helpers ----------------
#define CPA(dst, src) asm volatile("cp.async.cg.shared.global [%0], [%1], 16;\n" :: "r"(dst), "l"(src))
#define CPC() asm volatile("cp.async.commit_group;\n")
#define CPW(N) asm volatile("cp.async.wait_group %0;\n" :: "n"(N))
#define LDSM4(r0,r1,r2,r3,addr) asm volatile("ldmatrix.sync.aligned.m8n8.x4.shared.b16 {%0,%1,%2,%3}, [%4];\n" \
    : "=r"(r0),"=r"(r1),"=r"(r2),"=r"(r3) : "r"(addr))
#define LDSM4T(r0,r1,r2,r3,addr) asm volatile("ldmatrix.sync.aligned.m8n8.x4.trans.shared.b16 {%0,%1,%2,%3}, [%4];\n" \
    : "=r"(r0),"=r"(r1),"=r"(r2),"=r"(r3) : "r"(addr))

__device__ __forceinline__ uint32_t swz128(uint32_t x){ return x ^ ((x>>3)&0x70); }

__device__ __forceinline__ uint32_t packh2(float a, float b){
    __half2 h = __floats2half2_rn(a, b);
    return *reinterpret_cast<uint32_t*>(&h);
}
__device__ __forceinline__ void mma16816(float* c, const uint32_t* a, uint32_t b0, uint32_t b1){
    asm volatile("mma.sync.aligned.m16n8k16.row.col.f32.f16.f16.f32 "
        "{%0,%1,%2,%3}, {%4,%5,%6,%7}, {%8,%9}, {%0,%1,%2,%3};"
        : "+f"(c[0]), "+f"(c[1]), "+f"(c[2]), "+f"(c[3])
        : "r"(a[0]), "r"(a[1]), "r"(a[2]), "r"(a[3]), "r"(b0), "r"(b1));
}
__device__ __forceinline__ float blockSum(float v){
    __shared__ float sh[8];
    __shared__ float res;
    int lane = threadIdx.x & 31, w = threadIdx.x >> 5;
    #pragma unroll
    for (int o=16;o;o>>=1) v += __shfl_xor_sync(0xffffffffu, v, o);
    if (lane==0) sh[w] = v;
    __syncthreads();
    if (w==0){
        float x = (lane < 8) ? sh[lane] : 0.f;
        #pragma unroll
        for (int o=4;o;o>>=1) x += __shfl_xor_sync(0xffffffffu, x, o);
        if (lane==0) res = x;
    }
    __syncthreads();
    return res;
}

// ---------------- converts ----------------
__global__ void f2h4(const float* __restrict__ s, __half* __restrict__ d, int n){
    int i = (blockIdx.x*256 + threadIdx.x)*4;
    if (i < n){
        float4 v = *(const float4*)(s+i);
        *(__half2*)(d+i)   = __floats2half2_rn(v.x, v.y);
        *(__half2*)(d+i+2) = __floats2half2_rn(v.z, v.w);
    }
}
__global__ void convkv(const float* __restrict__ k, const float* __restrict__ v,
                       __half* __restrict__ kd, __half* __restrict__ vd){
    int idx = blockIdx.x*256 + threadIdx.x;
    if (idx >= BATCH*KLEN*NKV*(HD/2)) return;
    int d2  = idx & 31;
    int kvh = (idx>>5) & 7;
    int kk  = (idx>>8) & 2047;
    int bb  = idx>>19;
    size_t src = (((size_t)(bb*KLEN+kk)*NKV + kvh)*HD) + d2*2;
    size_t dst = (((size_t)(bb*NKV+kvh)*KLEN + kk)*HD) + d2*2;
    float2 kf = *(const float2*)(k+src);
    float2 vf = *(const float2*)(v+src);
    *(__half2*)(kd+dst) = __floats2half2_rn(kf.x, kf.y);
    *(__half2*)(vd+dst) = __floats2half2_rn(vf.x, vf.y);
}

// ---------------- RMSNorm ----------------
__global__ void rmsnorm_h(const float* __restrict__ x, const float* __restrict__ w,
                          __half* __restrict__ o)
{
    size_t row = blockIdx.x;
    const float* xr = x + row*HIDDEN;
    __half* orow = o + row*HIDDEN;
    float s = 0.f;
    for (int i=threadIdx.x; i<HIDDEN; i+=256){ float v = xr[i]; s += v*v; }
    s = blockSum(s);
    float rs = rsqrtf(s*(1.f/HIDDEN) + 1e-5f);
    for (int i=threadIdx.x; i<HIDDEN; i+=256) orow[i] = __float2half(xr[i]*rs*w[i]);
}

// ==================== tcgen05 GEMM, warp-specialized TMA pipeline ====================
#define TCSTAGE 65536
#define TC_SMEM (3*TCSTAGE + 2048)
#define EPITCH 33

#if HAS_TCGEN05
__device__ __forceinline__ uint32_t elect_one_pred(){
    uint32_t pred;
    asm volatile("{\n\t.reg .pred p;\n\telect.sync _|p, 0xFFFFFFFF;\n\tselp.b32 %0, 1, 0, p;\n\t}" : "=r"(pred));
    return pred;
}
#define MBARRIER_INIT(addr, cnt) \
    asm volatile("mbarrier.init.shared.b64 [%0], %1;" :: "r"((uint32_t)(addr)), "r"((uint32_t)(cnt)) : "memory")
#define MBARRIER_EXPECT_TX(addr, bytes) \
    asm volatile("mbarrier.arrive.expect_tx.shared.b64 _, [%0], %1;" :: "r"((uint32_t)(addr)), "r"((uint32_t)(bytes)) : "memory")
#define TMA_2D(smem_addr, map_ptr, cx, cy, mbar) \
    asm volatile("cp.async.bulk.tensor.2d.shared::cta.global.tile.mbarrier::complete_tx::bytes " \
        "[%0], [%1, {%2, %3}], [%4];" \
        :: "r"((uint32_t)(smem_addr)), "l"(map_ptr), "r"((int)(cx)), "r"((int)(cy)), \
           "r"((uint32_t)(mbar)) : "memory")
__device__ __forceinline__ void mbar_wait(uint32_t mbar, uint32_t phase){
    asm volatile(
        "{\n\t.reg .pred P1;\n\t"
        "WAIT_%=:\n\t"
        "mbarrier.try_wait.parity.acquire.cta.shared::cta.b64 P1, [%0], %1, 0x989680;\n\t"
        "@P1 bra.uni DONE_%=;\n\t"
        "bra.uni WAIT_%=;\n\t"
        "DONE_%=:\n\t}"
        :: "r"(mbar), "r"(phase) : "memory");
}
static __device__ __forceinline__ uint64_t make_desc_sw128(uint32_t addr){
    const uint64_t base =
        (uint64_t(2)  << 61) | (uint64_t(1) << 46) | (uint64_t(64) << 32) | (uint64_t(1) << 16);
    return base | ((uint64_t)(addr >> 4) & 0x3FFF);
}
#define IDESC_N256 ((1u<<4) | (32u<<17) | (8u<<24))
#define IDESC_N128 ((1u<<4) | (16u<<17) | (8u<<24))
__device__ __forceinline__ void mma_f16_ss(uint32_t d, uint64_t ad, uint64_t bd, uint32_t idesc, uint32_t en){
    asm volatile(
        "{\n\t.reg .pred p;\n\tsetp.ne.u32 p, %5, 0;\n\t"
        "tcgen05.mma.cta_group::1.kind::f16 [%0], %1, %2, %3, {%4,%4,%4,%4}, p;\n\t}"
        :: "r"(d), "l"(ad), "l"(bd), "r"(idesc), "r"(0u), "r"(en) : "memory");
}
#define LDTM32(r, tmem_addr) \
    asm volatile( \
        "tcgen05.ld.sync.aligned.32x32b.x32.b32 " \
        "{%0, %1, %2, %3, %4, %5, %6, %7, " \
        " %8, %9, %10, %11, %12, %13, %14, %15, " \
        " %16, %17, %18, %19, %20, %21, %22, %23, " \
        " %24, %25, %26, %27, %28, %29, %30, %31}, [%32];" \
        : "=r"((r)[0]),  "=r"((r)[1]),  "=r"((r)[2]),  "=r"((r)[3]), \
          "=r"((r)[4]),  "=r"((r)[5]),  "=r"((r)[6]),  "=r"((r)[7]), \
          "=r"((r)[8]),  "=r"((r)[9]),  "=r"((r)[10]), "=r"((r)[11]), \
          "=r"((r)[12]), "=r"((r)[13]), "=r"((r)[14]), "=r"((r)[15]), \
          "=r"((r)[16]), "=r"((r)[17]), "=r"((r)[18]), "=r"((r)[19]), \
          "=r"((r)[20]), "=r"((r)[21]), "=r"((r)[22]), "=r"((r)[23]), \
          "=r"((r)[24]), "=r"((r)[25]), "=r"((r)[26]), "=r"((r)[27]), \
          "=r"((r)[28]), "=r"((r)[29]), "=r"((r)[30]), "=r"((r)[31]) \
        : "r"(tmem_addr))
#endif

// mode 0: Ch=acc; 1: Cf=acc+Resf; 3: Ch=acc*0.125
__global__ __launch_bounds__(256,1)
void gemm_tc(float* __restrict__ Cf, __half* __restrict__ Ch,
             const float* __restrict__ Resf,
             int M, int N, int K, int mode,
             const __grid_constant__ CUtensorMap amap,
             const __grid_constant__ CUtensorMap bmap)
{
#if HAS_TCGEN05
    extern __shared__ char smraw[];
    uint32_t smem0 = (uint32_t)__cvta_generic_to_shared(smraw);
    uint32_t base  = (smem0 + 1023u) & ~1023u;
    char* gbase = smraw + (base - smem0);
    const uint32_t ctrl = base + 3*TCSTAGE;
    const uint32_t mbM = ctrl + 16;    // 3 mma-done barriers
    const uint32_t mbF = ctrl + 48;    // 3 full barriers
    const uint32_t mbX = ctrl + 80;    // final

    const int tid = threadIdx.x, lane = tid&31, warp = tid>>5;
    const int m0 = blockIdx.y*256, n0 = blockIdx.x*256;
    const int nkb = K >> 6;

    if (warp==0)
        asm volatile("tcgen05.alloc.cta_group::1.sync.aligned.shared::cta.b32 [%0], %1;"
            :: "r"(ctrl), "r"(512u) : "memory");
    if (tid==0){
        #pragma unroll
        for (int i=0;i<3;i++){ MBARRIER_INIT(mbM + i*8, 1); MBARRIER_INIT(mbF + i*8, 1); }
        MBARRIER_INIT(mbX, 1);
    }
    __syncthreads();
    uint32_t tmem; asm volatile("ld.shared.b32 %0, [%1];" : "=r"(tmem) : "r"(ctrl));

    uint32_t aAddr[3], bAddr[3];
    uint64_t aDesc[3], bDesc[3];
    #pragma unroll
    for (int s=0;s<3;s++){
        aAddr[s] = base + s*TCSTAGE;
        bAddr[s] = base + s*TCSTAGE + 32768;
        aDesc[s] = make_desc_sw128(aAddr[s]);
        bDesc[s] = make_desc_sw128(bAddr[s]);
    }

    if (warp==1){
        // producer: TMA loads
        if (elect_one_pred()){
            #pragma unroll
            for (int c=0;c<3;c++){
                if (c < nkb){
                    MBARRIER_EXPECT_TX(mbF + c*8, 65536);
                    TMA_2D(aAddr[c], &amap, c*64, m0, mbF + c*8);
                    TMA_2D(bAddr[c], &bmap, c*64, n0, mbF + c*8);
                }
            }
            for (int t=3; t<nkb; t++){
                const int st = t%3;
                mbar_wait(mbM + st*8, (uint32_t)(((t-3)/3)&1));
                MBARRIER_EXPECT_TX(mbF + st*8, 65536);
                TMA_2D(aAddr[st], &amap, t*64, m0, mbF + st*8);
                TMA_2D(bAddr[st], &bmap, t*64, n0, mbF + st*8);
            }
        }
    } else if (warp==0){
        // consumer: MMA issue
        asm volatile("tcgen05.fence::after_thread_sync;" ::: "memory");
        if (elect_one_pred()){
            for (int t=0; t<nkb; t++){
                const int st = t%3;
                mbar_wait(mbF + st*8, (uint32_t)((t/3)&1));
                #pragma unroll
                for (int hf=0; hf<2; hf++){
                    #pragma unroll
                    for (int kc=0;kc<4;kc++){
                        mma_f16_ss(tmem + hf*256,
                                   aDesc[st] + hf*1024 + kc*2,
                                   bDesc[st] + kc*2, IDESC_N256,
                                   (t>0 || kc>0) ? 1u : 0u);
                    }
                }
                asm volatile("tcgen05.commit.cta_group::1.mbarrier::arrive::one.shared::cluster.b64 [%0];"
                    :: "r"(mbM + (uint32_t)st*8) : "memory");
            }
            asm volatile("tcgen05.commit.cta_group::1.mbarrier::arrive::one.shared::cluster.b64 [%0];"
                :: "r"(mbX) : "memory");
        }
    }

    mbar_wait(mbX, 0u);
    asm volatile("fence.proxy.async.shared::cta;" ::: "memory");
    asm volatile("tcgen05.fence::after_thread_sync;" ::: "memory");
    __syncthreads();

    // epilogue: LDTM -> smem -> coalesced gmem
    float* sEp = (float*)gbase;
    const int hf  = warp>>2;
    const int wsb = warp&3;
    const int rr = tid>>3, c4 = (tid&7)*4;

    for (int cc=0; cc<8; cc++){
        uint32_t r[32];
        LDTM32(r, tmem + hf*256 + cc*32);
        asm volatile("tcgen05.wait::ld.sync.aligned;" ::: "memory");
        float* sp = sEp + (hf*128 + wsb*32 + lane)*EPITCH;
        #pragma unroll
        for (int j=0;j<32;j++) sp[j] = __uint_as_float(r[j]);
        __syncthreads();
        #pragma unroll
        for (int i=0;i<8;i++){
            int row = i*32 + rr;
            size_t go = (size_t)(m0 + row)*N + (n0 + cc*32 + c4);
            const float* s4 = sEp + row*EPITCH + c4;
            float v0=s4[0], v1=s4[1], v2=s4[2], v3=s4[3];
            if (mode==1){
                float4 rf = *(const float4*)(Resf + go);
                *(float4*)(Cf + go) = make_float4(v0+rf.x, v1+rf.y, v2+rf.z, v3+rf.w);
            } else if (mode==3){
                *(uint2*)(Ch + go) = make_uint2(packh2(v0*0.125f, v1*0.125f),
                                                packh2(v2*0.125f, v3*0.125f));
            } else {
                *(uint2*)(Ch + go) = make_uint2(packh2(v0,v1), packh2(v2,v3));
            }
        }
        __syncthreads();
    }

    asm volatile("tcgen05.fence::before_thread_sync;" ::: "memory");
    __syncthreads();
    if (warp==0)
        asm volatile("tcgen05.dealloc.cta_group::1.sync.aligned.b32 %0, %1;" :: "r"(tmem), "r"(512u));
#endif
}

// ==================== fused gate+up+SiLU, warp-specialized TMA pipeline ====================
__global__ __launch_bounds__(256,1)
void gemm_tc_gu(__half* __restrict__ Ch, int M, int N, int K,
                const __grid_constant__ CUtensorMap amap,
                const __grid_constant__ CUtensorMap gmap,
                const __grid_constant__ CUtensorMap umap)
{
#if HAS_TCGEN05
    extern __shared__ char smraw[];
    uint32_t smem0 = (uint32_t)__cvta_generic_to_shared(smraw);
    uint32_t base  = (smem0 + 1023u) & ~1023u;
    const uint32_t ctrl = base + 3*TCSTAGE;
    const uint32_t mbM = ctrl + 16;
    const uint32_t mbF = ctrl + 48;
    const uint32_t mbX = ctrl + 80;

    const int tid = threadIdx.x, lane = tid&31, warp = tid>>5;
    const int m0 = blockIdx.y*256, n0 = blockIdx.x*128;
    const int nkb = K >> 6;

    if (warp==0)
        asm volatile("tcgen05.alloc.cta_group::1.sync.aligned.shared::cta.b32 [%0], %1;"
            :: "r"(ctrl), "r"(512u) : "memory");
    if (tid==0){
        #pragma unroll
        for (int i=0;i<3;i++){ MBARRIER_INIT(mbM + i*8, 1); MBARRIER_INIT(mbF + i*8, 1); }
        MBARRIER_INIT(mbX, 1);
    }
    __syncthreads();
    uint32_t tmem; asm volatile("ld.shared.b32 %0, [%1];" : "=r"(tmem) : "r"(ctrl));

    uint32_t aAddr[3], gAddr[3], uAddr[3];
    uint64_t aDesc[3], gDesc[3], uDesc[3];
    #pragma unroll
    for (int s=0;s<3;s++){
        aAddr[s] = base + s*TCSTAGE;
        gAddr[s] = base + s*TCSTAGE + 32768;
        uAddr[s] = base + s*TCSTAGE + 49152;
        aDesc[s] = make_desc_sw128(aAddr[s]);
        gDesc[s] = make_desc_sw128(gAddr[s]);
        uDesc[s] = make_desc_sw128(uAddr[s]);
    }

    if (warp==1){
        if (elect_one_pred()){
            #pragma unroll
            for (int c=0;c<3;c++){
                if (c < nkb){
                    MBARRIER_EXPECT_TX(mbF + c*8, 65536);
                    TMA_2D(aAddr[c], &amap, c*64, m0, mbF + c*8);
                    TMA_2D(gAddr[c], &gmap, c*64, n0, mbF + c*8);
                    TMA_2D(uAddr[c], &umap, c*64, n0, mbF + c*8);
                }
            }
            for (int t=3; t<nkb; t++){
                const int st = t%3;
                mbar_wait(mbM + st*8, (uint32_t)(((t-3)/3)&1));
                MBARRIER_EXPECT_TX(mbF + st*8, 65536);
                TMA_2D(aAddr[st], &amap, t*64, m0, mbF + st*8);
                TMA_2D(gAddr[st], &gmap, t*64, n0, mbF + st*8);
                TMA_2D(uAddr[st], &umap, t*64, n0, mbF + st*8);
            }
        }
    } else if (warp==0){
        asm volatile("tcgen05.fence::after_thread_sync;" ::: "memory");
        if (elect_one_pred()){
            for (int t=0; t<nkb; t++){
                const int st = t%3;
                mbar_wait(mbF + st*8, (uint32_t)((t/3)&1));
                #pragma unroll
                for (int hf=0; hf<2; hf++){
                    #pragma unroll
                    for (int kc=0;kc<4;kc++){
                        uint32_t e = (t>0 || kc>0) ? 1u : 0u;
                        mma_f16_ss(tmem + hf*128,
                                   aDesc[st] + hf*1024 + kc*2,
                                   gDesc[st] + kc*2, IDESC_N128, e);
                        mma_f16_ss(tmem + 256 + hf*128,
                                   aDesc[st] + hf*1024 + kc*2,
                                   uDesc[st] + kc*2, IDESC_N128, e);
                    }
                }
                asm volatile("tcgen05.commit.cta_group::1.mbarrier::arrive::one.shared::cluster.b64 [%0];"
                    :: "r"(mbM + (uint32_t)st*8) : "memory");
            }
            asm volatile("tcgen05.commit.cta_group::1.mbarrier::arrive::one.shared::cluster.b64 [%0];"
                :: "r"(mbX) : "memory");
        }
    }

    mbar_wait(mbX, 0u);
    asm volatile("tcgen05.fence::after_thread_sync;" ::: "memory");
    __syncthreads();

    // epilogue: silu(gate)*up straight from TMEM, direct stores
    const int hf  = warp>>2;
    const int wsb = warp&3;
    const int row = hf*128 + wsb*32 + lane;

    #pragma unroll
    for (int cc=0; cc<4; cc++){
        uint32_t rg[32], ru[32];
        LDTM32(rg, tmem + hf*128 + cc*32);
        LDTM32(ru, tmem + 256 + hf*128 + cc*32);
        asm volatile("tcgen05.wait::ld.sync.aligned;" ::: "memory");
        __half* dst = Ch + (size_t)(m0 + row)*N + (n0 + cc*32);
        #pragma unroll
        for (int j=0;j<32;j+=2){
            float g0 = __uint_as_float(rg[j]),   g1 = __uint_as_float(rg[j+1]);
            float u0 = __uint_as_float(ru[j]),   u1 = __uint_as_float(ru[j+1]);
            float v0 = (g0/(1.f+__expf(-g0)))*u0;
            float v1 = (g1/(1.f+__expf(-g1)))*u1;
            *(__half2*)(dst + j) = __floats2half2_rn(v0, v1);
        }
    }

    asm volatile("tcgen05.fence::before_thread_sync;" ::: "memory");
    __syncthreads();
    if (warp==0)
        asm volatile("tcgen05.dealloc.cta_group::1.sync.aligned.b32 %0, %1;" :: "r"(tmem), "r"(512u));
#endif
}

// ---------------- fallback fp16 mma.sync GEMM ----------------
#define SPITCH 72
#define STAGEB (128*SPITCH*2)

__global__ __launch_bounds__(256,2)
void gemm16(const __half* __restrict__ A, const __half* __restrict__ B,
            float* __restrict__ Cf, __half* __restrict__ Ch,
            const __half* __restrict__ Resh, const float* __restrict__ Resf,
            int M, int N, int K, int mode)
{
    extern __shared__ __half smf[];
    uint32_t asBase = (uint32_t)__cvta_generic_to_shared(smf);
    uint32_t bsBase = asBase + 2*STAGEB;

    const int tid = threadIdx.x, lane = tid&31, warp = tid>>5;
    const int g = lane>>2, tg = lane&3;
    const int wm = (warp&1)*64, wn = (warp>>1)*32;
    const int m0 = blockIdx.y*128, n0 = blockIdx.x*128;

    const int crow = tid>>3;
    const int cchk = tid&7;
    const uint32_t sOff = (uint32_t)(crow*SPITCH*2 + cchk*16);
    const __half* aSrc = A + (size_t)(m0+crow)*K + cchk*8;
    const __half* bSrc = B + (size_t)(n0+crow)*K + cchk*8;

    float acc[4][4][4];
    #pragma unroll
    for (int i=0;i<4;i++)
        #pragma unroll
        for (int j=0;j<4;j++){ acc[i][j][0]=0.f; acc[i][j][1]=0.f; acc[i][j][2]=0.f; acc[i][j][3]=0.f; }

    const int nkb = K >> 6;
    {
        uint32_t ao = asBase + sOff, bo = bsBase + sOff;
        #pragma unroll
        for (int i=0;i<4;i++){
            CPA(ao + i*32*SPITCH*2, aSrc + (size_t)i*32*K);
            CPA(bo + i*32*SPITCH*2, bSrc + (size_t)i*32*K);
        }
        CPC();
    }

    for (int kb=0; kb<nkb; kb++){
        const int st = kb & 1;
        if (kb+1 < nkb){
            uint32_t ao = asBase + (st^1)*STAGEB + sOff;
            uint32_t bo = bsBase + (st^1)*STAGEB + sOff;
            const __half* ap = aSrc + (size_t)(kb+1)*64;
            const __half* bp = bSrc + (size_t)(kb+1)*64;
            #pragma unroll
            for (int i=0;i<4;i++){
                CPA(ao + i*32*SPITCH*2, ap + (size_t)i*32*K);
                CPA(bo + i*32*SPITCH*2, bp + (size_t)i*32*K);
            }
            CPC();
            CPW(1);
        } else {
            CPW(0);
        }
        __syncthreads();

        const uint32_t aW = asBase + st*STAGEB;
        const uint32_t bW = bsBase + st*STAGEB;
        #pragma unroll
        for (int kc=0;kc<4;kc++){
            uint32_t af[4][4], bf[2][4];
            #pragma unroll
            for (int mi=0;mi<4;mi++){
                int r = wm + mi*16 + (lane&15);
                int c = kc*16 + (lane>>4)*8;
                LDSM4(af[mi][0],af[mi][1],af[mi][2],af[mi][3], aW + (uint32_t)(r*SPITCH + c)*2);
            }
            #pragma unroll
            for (int nj=0;nj<2;nj++){
                int r = wn + nj*16 + (lane>>4)*8 + (lane&7);
                int c = kc*16 + ((lane>>3)&1)*8;
                LDSM4(bf[nj][0],bf[nj][1],bf[nj][2],bf[nj][3], bW + (uint32_t)(r*SPITCH + c)*2);
            }
            #pragma unroll
            for (int mi=0;mi<4;mi++){
                #pragma unroll
                for (int nj=0;nj<2;nj++){
                    mma16816(acc[mi][2*nj  ], af[mi], bf[nj][0], bf[nj][1]);
                    mma16816(acc[mi][2*nj+1], af[mi], bf[nj][2], bf[nj][3]);
                }
            }
        }
        __syncthreads();
    }

    #pragma unroll
    for (int mi=0;mi<4;mi++){
        #pragma unroll
        for (int ni=0;ni<4;ni++){
            int r0 = m0 + wm + mi*16 + g;
            int r1 = r0 + 8;
            int c  = n0 + wn + ni*8 + 2*tg;
            size_t o0 = (size_t)r0*N + c;
            size_t o1 = (size_t)r1*N + c;
            float v0=acc[mi][ni][0], v1=acc[mi][ni][1], v2=acc[mi][ni][2], v3=acc[mi][ni][3];
            if (mode == 1){
                v0 += Resf[o0]; v1 += Resf[o0+1]; v2 += Resf[o1]; v3 += Resf[o1+1];
                *(float2*)&Cf[o0] = make_float2(v0,v1);
                *(float2*)&Cf[o1] = make_float2(v2,v3);
            } else if (mode == 2){
                float g0 = __half2float(Resh[o0]), g1 = __half2float(Resh[o0+1]);
                float g2 = __half2float(Resh[o1]), g3 = __half2float(Resh[o1+1]);
                v0 *= g0/(1.f+__expf(-g0)); v1 *= g1/(1.f+__expf(-g1));
                v2 *= g2/(1.f+__expf(-g2)); v3 *= g3/(1.f+__expf(-g3));
                *(__half2*)&Ch[o0] = __floats2half2_rn(v0,v1);
                *(__half2*)&Ch[o1] = __floats2half2_rn(v2,v3);
            } else if (mode == 3){
                *(__half2*)&Ch[o0] = __floats2half2_rn(v0*0.125f, v1*0.125f);
                *(__half2*)&Ch[o1] = __floats2half2_rn(v2*0.125f, v3*0.125f);
            } else {
                *(__half2*)&Ch[o0] = __floats2half2_rn(v0,v1);
                *(__half2*)&Ch[o1] = __floats2half2_rn(v2,v3);
            }
        }
    }
}

// ---------------- flash attention (swizzled stages, occ 2) ----------------
#define FSTG 16384
#define FSMEM (4*FSTG)

__global__ __launch_bounds__(256,2)
void flash4(const __half* __restrict__ qh, const __half* __restrict__ kh,
            const __half* __restrict__ vh, __half* __restrict__ oh,
            const int* __restrict__ cuq, const int* __restrict__ cuk)
{
    extern __shared__ __half sm[];
    uint32_t ksBase = (uint32_t)__cvta_generic_to_shared(sm);
    uint32_t vsBase = ksBase + 2*FSTG;

    const int tid  = threadIdx.x;
    const int lane = tid & 31, warp = tid >> 5;
    const int g = lane >> 2, tg = lane & 3;
    const int bh = blockIdx.y;
    const int b = bh >> 5, h = bh & 31, kv = h >> 2;
    const int q0 = blockIdx.x * 128;
    const int wq = warp * 16;

    const int cq1 = cuq[1], cq2 = cuq[2];
    const int ck1 = cuk[1], ck2 = cuk[2];

    const int qg0 = q0 + wq + g, qg1 = qg0 + 8;
    const __half* qr0 = qh + ((size_t)(b*QLEN + qg0))*HIDDEN + h*HD;
    const __half* qr1 = qh + ((size_t)(b*QLEN + qg1))*HIDDEN + h*HD;
    uint32_t qf[4][4];
    #pragma unroll
    for (int kc=0;kc<4;kc++){
        qf[kc][0] = *(const uint32_t*)(qr0 + kc*16 + 2*tg);
        qf[kc][1] = *(const uint32_t*)(qr1 + kc*16 + 2*tg);
        qf[kc][2] = *(const uint32_t*)(qr0 + kc*16 + 2*tg + 8);
        qf[kc][3] = *(const uint32_t*)(qr1 + kc*16 + 2*tg + 8);
    }

    const int sq0 = (qg0>=cq1)+(qg0>=cq2);
    const int sq1 = (qg1>=cq1)+(qg1>=cq2);
    const int wlo = q0 + wq, whi = wlo + 15;
    const int sqa = (wlo>=cq1)+(wlo>=cq2);
    const int sqb = (whi>=cq1)+(whi>=cq2);

    float oacc[8][4];
    #pragma unroll
    for (int i=0;i<8;i++){ oacc[i][0]=0.f; oacc[i][1]=0.f; oacc[i][2]=0.f; oacc[i][3]=0.f; }
    float mr0 = -1e20f, mr1 = -1e20f, l0 = 0.f, l1 = 0.f;

    int segA = (q0>=cq1)+(q0>=cq2);
    int segB = (q0+127>=cq1)+(q0+127>=cq2);
    int klo, khi;
    if (segA == segB){
        int klos = (segA==0) ? 0 : ((segA==1) ? ck1 : ck2);
        int khis = (segA==0) ? ck1 : ((segA==1) ? ck2 : KLEN);
        klo = klos;
        khi = min(khis, q0+128);
    } else { klo = 0; khi = q0+128; }
    const int t0 = klo >> 7, t1 = (khi + 127) >> 7;

    const __half* kBase = kh + (size_t)(b*NKV+kv)*KLEN*HD;
    const __half* vBase = vh + (size_t)(b*NKV+kv)*KLEN*HD;
    const int crow = tid>>3, cchk = tid&7;
    uint32_t stOff[4];
    #pragma unroll
    for (int i=0;i<4;i++) stOff[i] = swz128((uint32_t)((crow + i*32)*128 + cchk*16));

    {
        const __half* kp = kBase + (size_t)(t0*128 + crow)*HD + cchk*8;
        const __half* vp = vBase + (size_t)(t0*128 + crow)*HD + cchk*8;
        #pragma unroll
        for (int i=0;i<4;i++){
            CPA(ksBase + stOff[i], kp + (size_t)i*32*HD);
            CPA(vsBase + stOff[i], vp + (size_t)i*32*HD);
        }
        CPC();
    }

    for (int t=t0; t<t1; t++){
        const int st = (t - t0) & 1;
        const int k0 = t << 7;
        if (t+1 < t1){
            uint32_t ko = ksBase + (st^1)*FSTG;
            uint32_t vo = vsBase + (st^1)*FSTG;
            const __half* kp = kBase + (size_t)((t+1)*128 + crow)*HD + cchk*8;
            const __half* vp = vBase + (size_t)((t+1)*128 + crow)*HD + cchk*8;
            #pragma unroll
            for (int i=0;i<4;i++){
                CPA(ko + stOff[i], kp + (size_t)i*32*HD);
                CPA(vo + stOff[i], vp + (size_t)i*32*HD);
            }
            CPC();
            CPW(1);
        } else {
            CPW(0);
        }
        __syncthreads();

        const uint32_t kW = ksBase + st*FSTG;
        const uint32_t vW = vsBase + st*FSTG;

        float sacc[16][4];
        #pragma unroll
        for (int ni=0;ni<16;ni++){ sacc[ni][0]=0.f; sacc[ni][1]=0.f; sacc[ni][2]=0.f; sacc[ni][3]=0.f; }
        #pragma unroll
        for (int kc=0;kc<4;kc++){
            #pragma unroll
            for (int nj=0;nj<8;nj++){
                uint32_t b0,b1,b2,b3;
                int r = nj*16 + (lane>>4)*8 + (lane&7);
                int cb = kc*32 + ((lane>>3)&1)*16;
                LDSM4(b0,b1,b2,b3, kW + swz128((uint32_t)(r*128 + cb)));
                mma16816(sacc[2*nj  ], qf[kc], b0, b1);
                mma16816(sacc[2*nj+1], qf[kc], b2, b3);
            }
        }

        int s_k0   = (k0>=ck1)+(k0>=ck2);
        int s_k127 = (k0+127>=ck1)+(k0+127>=ck2);
        bool fullok = (k0+127 <= wlo) && (s_k0==sqa) && (s_k127==sqa) && (sqa==sqb);
        if (!fullok){
            #pragma unroll
            for (int ni=0;ni<16;ni++){
                int kg = k0 + ni*8 + 2*tg;
                int sk0 = (kg>=ck1)+(kg>=ck2);
                int sk1 = (kg+1>=ck1)+(kg+1>=ck2);
                if (!((kg   <= qg0) && (sk0==sq0))) sacc[ni][0] = -1e30f;
                if (!((kg+1 <= qg0) && (sk1==sq0))) sacc[ni][1] = -1e30f;
                if (!((kg   <= qg1) && (sk0==sq1))) sacc[ni][2] = -1e30f;
                if (!((kg+1 <= qg1) && (sk1==sq1))) sacc[ni][3] = -1e30f;
            }
        }

        float tm0 = -1e20f, tm1 = -1e20f;
        #pragma unroll
        for (int ni=0;ni<16;ni++){
            tm0 = fmaxf(tm0, fmaxf(sacc[ni][0], sacc[ni][1]));
            tm1 = fmaxf(tm1, fmaxf(sacc[ni][2], sacc[ni][3]));
        }
        tm0 = fmaxf(tm0, __shfl_xor_sync(0xffffffffu, tm0, 1));
        tm0 = fmaxf(tm0, __shfl_xor_sync(0xffffffffu, tm0, 2));
        tm1 = fmaxf(tm1, __shfl_xor_sync(0xffffffffu, tm1, 1));
        tm1 = fmaxf(tm1, __shfl_xor_sync(0xffffffffu, tm1, 2));
        float mn0 = fmaxf(mr0, tm0), mn1 = fmaxf(mr1, tm1);
        float sc0 = __expf(mr0 - mn0), sc1 = __expf(mr1 - mn1);
        l0 *= sc0; l1 *= sc1;
        #pragma unroll
        for (int nd=0;nd<8;nd++){
            oacc[nd][0]*=sc0; oacc[nd][1]*=sc0; oacc[nd][2]*=sc1; oacc[nd][3]*=sc1;
        }
        uint32_t pf[8][4];
        float rs0 = 0.f, rs1 = 0.f;
        #pragma unroll
        for (int j=0;j<8;j++){
            float p00 = __expf(sacc[2*j][0]-mn0),   p01 = __expf(sacc[2*j][1]-mn0);
            float p10 = __expf(sacc[2*j][2]-mn1),   p11 = __expf(sacc[2*j][3]-mn1);
            float q00 = __expf(sacc[2*j+1][0]-mn0), q01 = __expf(sacc[2*j+1][1]-mn0);
            float q10 = __expf(sacc[2*j+1][2]-mn1), q11 = __expf(sacc[2*j+1][3]-mn1);
            rs0 += p00+p01+q00+q01;
            rs1 += p10+p11+q10+q11;
            pf[j][0] = packh2(p00,p01);
            pf[j][1] = packh2(p10,p11);
            pf[j][2] = packh2(q00,q01);
            pf[j][3] = packh2(q10,q11);
        }
        rs0 += __shfl_xor_sync(0xffffffffu, rs0, 1);
        rs0 += __shfl_xor_sync(0xffffffffu, rs0, 2);
        rs1 += __shfl_xor_sync(0xffffffffu, rs1, 1);
        rs1 += __shfl_xor_sync(0xffffffffu, rs1, 2);
        l0 += rs0; l1 += rs1;
        mr0 = mn0; mr1 = mn1;

        #pragma unroll
        for (int j=0;j<8;j++){
            #pragma unroll
            for (int dq=0;dq<4;dq++){
                uint32_t b0,b1,b2,b3;
                int r = j*16 + ((lane>>3)&1)*8 + (lane&7);
                int cb = dq*32 + (lane>>4)*16;
                LDSM4T(b0,b1,b2,b3, vW + swz128((uint32_t)(r*128 + cb)));
                mma16816(oacc[2*dq  ], pf[j], b0, b1);
                mma16816(oacc[2*dq+1], pf[j], b2, b3);
            }
        }
        __syncthreads();
    }

    float inv0 = (l0 > 0.f) ? 1.f/l0 : 0.f;
    float inv1 = (l1 > 0.f) ? 1.f/l1 : 0.f;
    __half* or0 = oh + ((size_t)(b*QLEN + qg0))*HIDDEN + h*HD;
    __half* or1 = oh + ((size_t)(b*QLEN + qg1))*HIDDEN + h*HD;
    #pragma unroll
    for (int nd=0;nd<8;nd++){
        int c = nd*8 + 2*tg;
        *(__half2*)&or0[c] = __floats2half2_rn(oacc[nd][0]*inv0, oacc[nd][1]*inv0);
        *(__half2*)&or1[c] = __floats2half2_rn(oacc[nd][2]*inv1, oacc[nd][3]*inv1);
    }
}

// ---------------- host tensormap helper ----------------
typedef CUresult (*EncTiledFn)(CUtensorMap*, CUtensorMapDataType, cuuint32_t, void*,
                               const cuuint64_t*, const cuuint64_t*, const cuuint32_t*, const cuuint32_t*,
                               CUtensorMapInterleave, CUtensorMapSwizzle,
                               CUtensorMapL2promotion, CUtensorMapFloatOOBfill);

static bool enc_map(EncTiledFn enc, CUtensorMap* m, void* ptr, uint64_t Kdim, uint64_t Ndim, uint32_t box1){
    cuuint64_t dims[2]    = {(cuuint64_t)Kdim, (cuuint64_t)Ndim};
    cuuint64_t strides[1] = {(cuuint64_t)(Kdim*2)};
    cuuint32_t box[2]     = {64u, box1};
    cuuint32_t es[2]      = {1u, 1u};
    return enc(m, CU_TENSOR_MAP_DATA_TYPE_UINT16, 2, ptr, dims, strides, box, es,
               CU_TENSOR_MAP_INTERLEAVE_NONE, CU_TENSOR_MAP_SWIZZLE_128B,
               CU_TENSOR_MAP_L2_PROMOTION_L2_128B, CU_TENSOR_MAP_FLOAT_OOB_FILL_NONE) == CUDA_SUCCESS;
}

// ---------------- launch ----------------
extern "C" void kernel_launch(void* const* d_in, const int* in_sizes, int n_in,
                              void* d_out, int out_size)
{
    const float* hs   = (const float*)d_in[0];
    const float* kst  = (const float*)d_in[1];
    const float* vst  = (const float*)d_in[2];
    const float* wln1 = (const float*)d_in[4];
    const float* wln2 = (const float*)d_in[5];
    const float* wq   = (const float*)d_in[6];
    const float* wo   = (const float*)d_in[7];
    const float* wg   = (const float*)d_in[8];
    const float* wu   = (const float*)d_in[9];
    const float* wd   = (const float*)d_in[10];
    const int*   cuq  = (const int*)d_in[11];
    const int*   cuk  = (const int*)d_in[12];
    float* out = (float*)d_out;

    __half *wqh,*woh,*wgh,*wuh,*wdh,*kh,*vh,*n1h,*qh,*ath,*n2h,*gth,*ach;
    float *hid;
    cudaGetSymbolAddress((void**)&wqh, g_wqh);
    cudaGetSymbolAddress((void**)&woh, g_woh);
    cudaGetSymbolAddress((void**)&wgh, g_wgh);
    cudaGetSymbolAddress((void**)&wuh, g_wuh);
    cudaGetSymbolAddress((void**)&wdh, g_wdh);
    cudaGetSymbolAddress((void**)&kh,  g_kh);
    cudaGetSymbolAddress((void**)&vh,  g_vh);
    cudaGetSymbolAddress((void**)&n1h, g_n1h);
    cudaGetSymbolAddress((void**)&qh,  g_qh);
    cudaGetSymbolAddress((void**)&ath, g_ath);
    cudaGetSymbolAddress((void**)&n2h, g_n2h);
    cudaGetSymbolAddress((void**)&gth, g_gth);
    cudaGetSymbolAddress((void**)&ach, g_ach);
    cudaGetSymbolAddress((void**)&hid, g_hid);

    cudaFuncAttributes fa; fa.numRegs = 0;
    cudaFuncGetAttributes(&fa, (const void*)gemm_tc);
    bool use_tc = (fa.numRegs > 32);

    CUtensorMap mAn1{}, mAat{}, mAn2{}, mAac{}, mWq{}, mWo{}, mWg{}, mWu{}, mWd{};
    if (use_tc){
        void* p = nullptr;
        cudaDriverEntryPointQueryResult st;
        if (cudaGetDriverEntryPoint("cuTensorMapEncodeTiled", &p, cudaEnableDefault, &st) == cudaSuccess
            && st == cudaDriverEntryPointSuccess && p){
            EncTiledFn enc = (EncTiledFn)p;
            bool ok = enc_map(enc, &mAn1, n1h, HIDDEN, MTOT, 256)
                   && enc_map(enc, &mAat, ath, HIDDEN, MTOT, 256)
                   && enc_map(enc, &mAn2, n2h, HIDDEN, MTOT, 256)
                   && enc_map(enc, &mAac, ach, INTER,  MTOT, 256)
                   && enc_map(enc, &mWq,  wqh, HIDDEN, HIDDEN, 256)
                   && enc_map(enc, &mWo,  woh, HIDDEN, HIDDEN, 256)
                   && enc_map(enc, &mWg,  wgh, HIDDEN, INTER, 128)
                   && enc_map(enc, &mWu,  wuh, HIDDEN, INTER, 128)
                   && enc_map(enc, &mWd,  wdh, INTER,  HIDDEN, 256);
            if (!ok) use_tc = false;
        } else {
            use_tc = false;
        }
    }

    cudaFuncSetAttribute(flash4, cudaFuncAttributeMaxDynamicSharedMemorySize, FSMEM);
    if (use_tc){
        cudaFuncSetAttribute(gemm_tc,    cudaFuncAttributeMaxDynamicSharedMemorySize, TC_SMEM);
        cudaFuncSetAttribute(gemm_tc_gu, cudaFuncAttributeMaxDynamicSharedMemorySize, TC_SMEM);
    } else {
        cudaFuncSetAttribute(gemm16, cudaFuncAttributeMaxDynamicSharedMemorySize, 4*STAGEB);
    }

    const int HH = HIDDEN*HIDDEN, IH = INTER*HIDDEN;

    cudaStream_t sB;
    cudaStreamCreateWithFlags(&sB, cudaStreamNonBlocking);
    cudaEvent_t eF, eQ, eK, eJ;
    cudaEventCreateWithFlags(&eF, cudaEventDisableTiming);
    cudaEventCreateWithFlags(&eQ, cudaEventDisableTiming);
    cudaEventCreateWithFlags(&eK, cudaEventDisableTiming);
    cudaEventCreateWithFlags(&eJ, cudaEventDisableTiming);
    cudaEventRecord(eF, 0);
    cudaStreamWaitEvent(sB, eF, 0);

    f2h4<<<(HH/4+255)/256, 256, 0, sB>>>(wq, wqh, HH);
    cudaEventRecord(eQ, sB);
    rmsnorm_h<<<MTOT, 256>>>(hs, wln1, n1h);
    convkv<<<(BATCH*KLEN*NKV*(HD/2)+255)/256, 256, 0, sB>>>(kst, vst, kh, vh);
    cudaEventRecord(eK, sB);

    cudaStreamWaitEvent(0, eQ, 0);
    if (use_tc)
        gemm_tc<<<dim3(HIDDEN/256, MTOT/256), 256, TC_SMEM>>>(nullptr, qh, nullptr, MTOT, HIDDEN, HIDDEN, 3, mAn1, mWq);
    else
        gemm16<<<dim3(HIDDEN/128, MTOT/128), 256, 4*STAGEB>>>(n1h, wqh, nullptr, qh, nullptr, nullptr, MTOT, HIDDEN, HIDDEN, 3);

    cudaStreamWaitEvent(0, eK, 0);
    flash4<<<dim3(QLEN/128, BATCH*NHEADS), 256, FSMEM>>>(qh, kh, vh, ath, cuq, cuk);

    f2h4<<<(HH/4+255)/256, 256, 0, sB>>>(wo, woh, HH);
    f2h4<<<(IH/4+255)/256, 256, 0, sB>>>(wg, wgh, IH);
    f2h4<<<(IH/4+255)/256, 256, 0, sB>>>(wu, wuh, IH);
    f2h4<<<(IH/4+255)/256, 256, 0, sB>>>(wd, wdh, IH);
    cudaEventRecord(eJ, sB);
    cudaStreamWaitEvent(0, eJ, 0);

    if (use_tc){
        gemm_tc<<<dim3(HIDDEN/256, MTOT/256), 256, TC_SMEM>>>(hid, nullptr, hs, MTOT, HIDDEN, HIDDEN, 1, mAat, mWo);
        rmsnorm_h<<<MTOT, 256>>>(hid, wln2, n2h);
        gemm_tc_gu<<<dim3(INTER/128, MTOT/256), 256, TC_SMEM>>>(ach, MTOT, INTER, HIDDEN, mAn2, mWg, mWu);
        gemm_tc<<<dim3(HIDDEN/256, MTOT/256), 256, TC_SMEM>>>(out, nullptr, hid, MTOT, HIDDEN, INTER, 1, mAac, mWd);
    } else {
        gemm16<<<dim3(HIDDEN/128, MTOT/128), 256, 4*STAGEB>>>(ath, woh, hid, nullptr, nullptr, hs, MTOT, HIDDEN, HIDDEN, 1);
        rmsnorm_h<<<MTOT, 256>>>(hid, wln2, n2h);
        gemm16<<<dim3(INTER/128, MTOT/128), 256, 4*STAGEB>>>(n2h, wgh, nullptr, gth, nullptr, nullptr, MTOT, INTER, HIDDEN, 0);
        gemm16<<<dim3(INTER/128, MTOT/128), 256, 4*STAGEB>>>(n2h, wuh, nullptr, ach, gth, nullptr, MTOT, INTER, HIDDEN, 2);
        gemm16<<<dim3(HIDDEN/128, MTOT/128), 256, 4*STAGEB>>>(ach, wdh, out, nullptr, nullptr, hid, MTOT, HIDDEN, INTER, 1);
    }

    cudaEventDestroy(eF);
    cudaEventDestroy(eQ);
    cudaEventDestroy(eK);
    cudaEventDestroy(eJ);
    cudaStreamDestroy(sB);
}